// round 14
// baseline (speedup 1.0000x reference)
#include <cuda_runtime.h>
#include <math.h>

#define NS 512
#define DD 400
#define HH 400
#define HP 416   // padded hidden dim for the pair loop; pad rows stay zero

typedef unsigned long long u64;

// ---- scratch (no allocations; __device__ globals are zero-initialized) ----
__device__ float  g_hxT[HP * NS];   // [h][sample]; rows 400..415 never written
__device__ float  g_hyT[HP * NS];   // b1 folded in; rows 400..415 zero
__device__ u64    g_w2h[HP];        // dup'd (W2/2, W2/2); pad zero
__device__ float  g_rx[NS];         // sum_h hx[j,h]*W2[h]      (re-zeroed by finalize)
__device__ float  g_ry[NS];         // sum_h (hy[i,h]+b1)*W2[h] (re-zeroed by finalize)
__device__ float  g_expsum[NS];     // per-row sum of exp(T1) = 1 + e^v
__device__ double g_tsum;           // sum of all T1
__device__ double g_dsum;           // sum of diag T1 (== T0 sum)
__device__ int    g_cnt = 0;

// ---- packed f32x2 helpers (sm_10x) ----
#define PACK2(d, lo, hi) \
    asm("mov.b64 %0, {%1,%2};" : "=l"(d) : "f"(lo), "f"(hi))
#define FMA2(acc, a, b) \
    asm("fma.rn.f32x2 %0, %1, %2, %0;" : "+l"(acc) : "l"(a), "l"(b))
// acc2 += |y2 + x2| * w2   (componentwise; abs via sign-mask AND)
#define ABS_FMA2(acc, y2, x2, w2)                       \
    asm("{\n\t"                                         \
        ".reg .b64 t;\n\t"                              \
        "add.rn.f32x2 t, %1, %2;\n\t"                   \
        "and.b64 t, t, 0x7FFFFFFF7FFFFFFF;\n\t"         \
        "fma.rn.f32x2 %0, t, %3, %0;\n\t"               \
        "}" : "+l"(acc) : "l"(y2), "l"(x2), "l"(w2))

// ======================================================================
// Kernel 1: dual GEMM, whole-panel smem, flat barrier-free mainloop.
//   z=0: g_hxT[h][m] = x @ W1x^T;        g_rx[m] += row-dot with W2
//   z=1: g_hyT[h][m] = y @ W1y^T + b1;   g_ry[m] += row-dot with W2
// Tile 32m x 32h, 256 threads, thread tile 2h x 2m. Grid (16,13,2)=416.
// Dynamic smem 100 KB (A panel [400][32] + W panel [400][32]) -> 2 blocks/SM.
// ======================================================================
#define G_SMEM_BYTES (2 * DD * 32 * 4)   // 102,400 B

__global__ void __launch_bounds__(256, 1)
gemm_h_kernel(const float* __restrict__ x,
              const float* __restrict__ y,
              const float* __restrict__ W1,
              const float* __restrict__ b1,
              const float* __restrict__ W2) {
    extern __shared__ __align__(16) char gsm[];
    float* As = reinterpret_cast<float*>(gsm);            // [400][32]
    float* Hs = As + DD * 32;                             // [400][32]

    const int z   = blockIdx.z;
    const int tid = threadIdx.x;   // 256

    if (z == 0 && blockIdx.x == 0 && blockIdx.y == 0) {
        g_expsum[tid] = 0.f; g_expsum[tid + 256] = 0.f;
        for (int r = tid; r < HP; r += 256) {
            float w = (r < HH) ? W2[r] * 0.5f : 0.f;
            u64 wd; PACK2(wd, w, w);
            g_w2h[r] = wd;
        }
        if (tid == 0) { g_tsum = 0.0; g_dsum = 0.0; g_cnt = 0; }
    }

    const float* A   = z ? y : x;
    const int   woff = z ? DD : 0;
    float*      outT = z ? g_hyT : g_hxT;
    float*      rdot = z ? g_ry  : g_rx;

    const int m0 = blockIdx.x * 32;
    const int h0 = blockIdx.y * 32;

    // ---- bulk transpose-load: A rows (coalesced along k) -> As[k][m] ----
    for (int idx = tid; idx < 32 * 100; idx += 256) {
        int m = idx / 100, q = idx % 100;
        float4 v = *reinterpret_cast<const float4*>(&A[(m0 + m) * DD + q * 4]);
        As[(q * 4 + 0) * 32 + m] = v.x;
        As[(q * 4 + 1) * 32 + m] = v.y;
        As[(q * 4 + 2) * 32 + m] = v.z;
        As[(q * 4 + 3) * 32 + m] = v.w;
    }
    for (int idx = tid; idx < 32 * 100; idx += 256) {
        int h = idx / 100, q = idx % 100;
        float4 v = make_float4(0.f, 0.f, 0.f, 0.f);
        if (h0 + h < HH)
            v = *reinterpret_cast<const float4*>(&W1[(h0 + h) * (2 * DD) + woff + q * 4]);
        Hs[(q * 4 + 0) * 32 + h] = v.x;
        Hs[(q * 4 + 1) * 32 + h] = v.y;
        Hs[(q * 4 + 2) * 32 + h] = v.z;
        Hs[(q * 4 + 3) * 32 + h] = v.w;
    }
    __syncthreads();   // only barrier before epilogue

    // ---- flat mainloop: 400 iterations, no barriers ----
    const int tx = tid & 15;        // m pair: 2 m each
    const int ty = tid >> 4;        // h pair: 2 h each
    const u64*    ax = reinterpret_cast<const u64*>(As) + tx;     // +k*16
    const float2* hy = reinterpret_cast<const float2*>(Hs) + ty;  // +k*16

    u64 acc0 = 0, acc1 = 0;
    #pragma unroll 8
    for (int k = 0; k < DD; k++) {
        u64    a2 = ax[k * 16];
        float2 h2 = hy[k * 16];
        u64 hd0, hd1;
        PACK2(hd0, h2.x, h2.x);
        PACK2(hd1, h2.y, h2.y);
        FMA2(acc0, hd0, a2);
        FMA2(acc1, hd1, a2);
    }

    // ---- epilogue: b1 add, store, row-dot smem reduce ----
    __shared__ float rsum[32];
    if (tid < 32) rsum[tid] = 0.f;
    __syncthreads();

    float2 v0 = *reinterpret_cast<float2*>(&acc0);   // h = h0+ty*2
    float2 v1 = *reinterpret_cast<float2*>(&acc1);   // h = h0+ty*2+1
    const int ha = h0 + ty * 2, hb = ha + 1;
    const bool va = ha < HH, vb = hb < HH;
    if (z) {
        if (va) { float b = b1[ha]; v0.x += b; v0.y += b; }
        if (vb) { float b = b1[hb]; v1.x += b; v1.y += b; }
    }
    if (va) *reinterpret_cast<float2*>(&outT[ha * NS + m0 + tx * 2]) = v0;
    if (vb) *reinterpret_cast<float2*>(&outT[hb * NS + m0 + tx * 2]) = v1;
    const float wa = va ? W2[ha] : 0.f;
    const float wb = vb ? W2[hb] : 0.f;
    atomicAdd(&rsum[tx * 2 + 0], v0.x * wa + v1.x * wb);
    atomicAdd(&rsum[tx * 2 + 1], v0.y * wa + v1.y * wb);
    __syncthreads();
    if (tid < 32) atomicAdd(&rdot[m0 + tid], rsum[tid]);
}

// ======================================================================
// Kernel 2: pair abs-dot, whole-panel smem, flat barrier-free mainloop.
//   A[i,j] = sum_h |y[h,i] + x[h,j]| * (W2[h]/2)
//   v[i,j] = 0.5*(g_ry[i] + g_rx[j]) + A[i,j] + b2
// Tile 32i x 32j, 256 threads, thread tile 2i x 2j. Grid (16,16)=256.
// Dynamic smem 107 KB (x [416][32], y [416][32], w [416] u64) -> 2 blocks/SM.
// Conflict-free: x u64 @ tx*8B = 128B/16 lanes; y float2 @ ty*8B broadcast.
// ======================================================================
#define P_XS_F   (HP * 32)
#define P_YS_OFF (P_XS_F * 4)
#define P_WS_OFF (P_YS_OFF + P_XS_F * 4)
#define P_SMEM_BYTES (P_WS_OFF + HP * 8)   // 109,824 B

__global__ void __launch_bounds__(256, 1)
pair_kernel(const float* __restrict__ b2p,
            float* __restrict__ out) {
    extern __shared__ __align__(16) char psm[];
    float* Xs = reinterpret_cast<float*>(psm);              // [416][32]
    float* Ys = reinterpret_cast<float*>(psm + P_YS_OFF);   // [416][32]
    u64*   Ws = reinterpret_cast<u64*>(psm + P_WS_OFF);     // [416]

    const int j0  = blockIdx.x * 32;
    const int i0  = blockIdx.y * 32;
    const int tid = threadIdx.x;    // 256

    // ---- bulk load (coalesced) ----
    for (int idx = tid; idx < HP * 8; idx += 256) {
        int k = idx >> 3, q = idx & 7;
        *reinterpret_cast<float4*>(&Xs[k * 32 + q * 4]) =
            *reinterpret_cast<const float4*>(&g_hxT[k * NS + j0 + q * 4]);
    }
    for (int idx = tid; idx < HP * 8; idx += 256) {
        int k = idx >> 3, q = idx & 7;
        *reinterpret_cast<float4*>(&Ys[k * 32 + q * 4]) =
            *reinterpret_cast<const float4*>(&g_hyT[k * NS + i0 + q * 4]);
    }
    for (int idx = tid; idx < HP; idx += 256) Ws[idx] = g_w2h[idx];
    __syncthreads();   // only barrier before epilogue

    // ---- flat mainloop: 416 iterations, no barriers ----
    const int tx = tid & 15;        // j pair: 2 j each
    const int ty = tid >> 4;        // i pair: 2 i each
    const u64*    xr = reinterpret_cast<const u64*>(Xs) + tx;     // +k*16
    const float2* yr = reinterpret_cast<const float2*>(Ys) + ty;  // +k*16

    u64 acc0 = 0, acc1 = 0;         // i0+ty*2, i0+ty*2+1 (each packs 2 j)
    #pragma unroll 8
    for (int k = 0; k < HP; k++) {
        u64    xq = xr[k * 16];
        float2 yv = yr[k * 16];
        u64    wv = Ws[k];
        u64 yd0, yd1;
        PACK2(yd0, yv.x, yv.x);
        PACK2(yd1, yv.y, yv.y);
        ABS_FMA2(acc0, yd0, xq, wv);
        ABS_FMA2(acc1, yd1, xq, wv);
    }

    // ---- fused epilogue ----
    const float b2 = b2p[0];
    const float2 rx = *reinterpret_cast<const float2*>(&g_rx[j0 + tx * 2]);
    const float rxq[2] = {rx.x, rx.y};
    float tSum = 0.f, dSum = 0.f;

    #pragma unroll
    for (int ii = 0; ii < 2; ii++) {
        const int i = i0 + ty * 2 + ii;
        const float ry = g_ry[i];
        float2 pv = *reinterpret_cast<float2*>(ii ? &acc1 : &acc0);
        float aq[2] = {pv.x, pv.y};
        float eRow = 0.f;
        #pragma unroll
        for (int q = 0; q < 2; q++) {
            float v = 0.5f * (ry + rxq[q]) + aq[q] + b2;
            float tt = fmaxf(v, 0.f) + log1pf(expf(-fabsf(v)));
            eRow += 1.f + expf(v);            // exp(softplus(v)) == 1 + e^v
            tSum += tt;
            if (j0 + tx * 2 + q == i) dSum += tt;
        }
        // row partial over the 16 j-lanes (lanes 0-15 / 16-31 share ty)
        #pragma unroll
        for (int o = 8; o; o >>= 1)
            eRow += __shfl_down_sync(0xffffffffu, eRow, o, 16);
        if (tx == 0) atomicAdd(&g_expsum[i], eRow);
    }

    // block totals
    const int wid = tid >> 5, lane = tid & 31;
    #pragma unroll
    for (int o = 16; o; o >>= 1) {
        tSum += __shfl_down_sync(0xffffffffu, tSum, o);
        dSum += __shfl_down_sync(0xffffffffu, dSum, o);
    }
    __shared__ float wsum[8], wdia[8];
    if (lane == 0) { wsum[wid] = tSum; wdia[wid] = dSum; }
    __syncthreads();
    if (tid == 0) {
        float ts = 0.f, ds = 0.f;
        #pragma unroll
        for (int w = 0; w < 8; w++) { ts += wsum[w]; ds += wdia[w]; }
        atomicAdd(&g_tsum, (double)ts);
        atomicAdd(&g_dsum, (double)ds);
    }

    // ---- last block finalizes (double precision combine) ----
    __threadfence();
    __shared__ int ticket;
    if (tid == 0) ticket = atomicAdd(&g_cnt, 1);
    __syncthreads();
    if (ticket == 16 * 16 - 1) {
        g_rx[tid] = 0.f; g_rx[tid + 256] = 0.f;
        g_ry[tid] = 0.f; g_ry[tid + 256] = 0.f;
        double ls = log((double)g_expsum[tid]) + log((double)g_expsum[tid + 256]);
        #pragma unroll
        for (int o = 16; o; o >>= 1)
            ls += __shfl_down_sync(0xffffffffu, ls, o);
        __shared__ double lw[8];
        if (lane == 0) lw[wid] = ls;
        __syncthreads();
        if (tid == 0) {
            double lsum = 0.0;
            #pragma unroll
            for (int w = 0; w < 8; w++) lsum += lw[w];
            const double n = (double)NS;
            double t0_mean = g_dsum / n;
            out[0] = (float)(t0_mean - (lsum / n - log(n)));   // lower bound
            out[1] = (float)(t0_mean - g_tsum / (n * n));      // upper bound
            g_cnt = 0;
        }
    }
}

// ======================================================================
extern "C" void kernel_launch(void* const* d_in, const int* in_sizes, int n_in,
                              void* d_out, int out_size) {
    const float* x  = (const float*)d_in[0];
    const float* y  = (const float*)d_in[1];
    const float* W1 = (const float*)d_in[2];
    const float* b1 = (const float*)d_in[3];
    const float* W2 = (const float*)d_in[4];
    const float* b2 = (const float*)d_in[5];
    float* out = (float*)d_out;

    // host-side attribute set, idempotent; legal under graph capture
    static bool attr_done = false;
    if (!attr_done) {
        cudaFuncSetAttribute(gemm_h_kernel,
                             cudaFuncAttributeMaxDynamicSharedMemorySize,
                             G_SMEM_BYTES);
        cudaFuncSetAttribute(pair_kernel,
                             cudaFuncAttributeMaxDynamicSharedMemorySize,
                             P_SMEM_BYTES);
        attr_done = true;
    }

    dim3 ggrid(NS / 32, HP / 32, 2);          // (16, 13, 2) = 416 blocks
    gemm_h_kernel<<<ggrid, 256, G_SMEM_BYTES>>>(x, y, W1, b1, W2);

    dim3 pgrid(NS / 32, NS / 32);             // (16, 16) = 256 blocks
    pair_kernel<<<pgrid, 256, P_SMEM_BYTES>>>(b2, out);
}

// round 16
// speedup vs baseline: 1.5810x; 1.5810x over previous
#include <cuda_runtime.h>
#include <math.h>

#define NS 512
#define DD 400
#define HH 400
#define HP 416   // padded hidden dim (26 * 16); pad rows stay zero

typedef unsigned long long u64;

// ---- scratch (no allocations; __device__ globals are zero-initialized) ----
__device__ float  g_hxT[HP * NS];   // [h][sample]; rows 400..415 never written
__device__ u64    g_hyTd[HP * NS];  // dup'd (y,y) per element (b1 folded); pad zero
__device__ u64    g_w2h[HP];        // dup'd (W2/2, W2/2); pad zero
__device__ float  g_pA[4][NS * NS]; // per-split partial abs-dot slices
__device__ int    g_tcnt[128];      // per-tile arrival counters (reset by winners)
__device__ float  g_rx[NS];         // sum_h hx[j,h]*W2[h]      (re-zeroed by finalize)
__device__ float  g_ry[NS];         // sum_h (hy[i,h]+b1)*W2[h] (re-zeroed by finalize)
__device__ float  g_expsum[NS];     // per-row sum of exp(T1) = 1 + e^v
__device__ double g_tsum;           // sum of all T1
__device__ double g_dsum;           // sum of diag T1 (== T0 sum)
__device__ int    g_cnt = 0;

// ---- packed f32x2 helpers (sm_10x) ----
#define PACK2(d, lo, hi) \
    asm("mov.b64 %0, {%1,%2};" : "=l"(d) : "f"(lo), "f"(hi))
#define FMA2(acc, a, b) \
    asm("fma.rn.f32x2 %0, %1, %2, %0;" : "+l"(acc) : "l"(a), "l"(b))
// acc2 += |y2 + x2| * w2   (componentwise; abs via sign-mask AND)
#define ABS_FMA2(acc, y2, x2, w2)                       \
    asm("{\n\t"                                         \
        ".reg .b64 t;\n\t"                              \
        "add.rn.f32x2 t, %1, %2;\n\t"                   \
        "and.b64 t, t, 0x7FFFFFFF7FFFFFFF;\n\t"         \
        "fma.rn.f32x2 %0, t, %3, %0;\n\t"               \
        "}" : "+l"(acc) : "l"(y2), "l"(x2), "l"(w2))

// ======================================================================
// Kernel 1: dual GEMM (R12 version, verbatim, for attribution).
//   z=0: g_hxT[h][m] = x @ W1x^T;          g_rx += row-dot
//   z=1: g_hyTd[h][m] = dup(y@W1y + b1);   g_ry += row-dot
// Tile 64m x 32h, BK=16, 128 threads, thread tile 4h x 2m-pairs.
// Grid (8, 13, 2) = 208 blocks.
// ======================================================================
__global__ void __launch_bounds__(128)
gemm_h_kernel(const float* __restrict__ x,
              const float* __restrict__ y,
              const float* __restrict__ W1,
              const float* __restrict__ b1,
              const float* __restrict__ W2) {
    const int z = blockIdx.z;

    if (z == 0 && blockIdx.x == 0 && blockIdx.y == 0) {
        #pragma unroll
        for (int r = 0; r < 4; r++) g_expsum[threadIdx.x + r * 128] = 0.f;
        for (int r = threadIdx.x; r < HP; r += 128) {
            float w = (r < HH) ? W2[r] * 0.5f : 0.f;
            u64 wd; PACK2(wd, w, w);
            g_w2h[r] = wd;
        }
        if (threadIdx.x == 0) { g_tsum = 0.0; g_dsum = 0.0; g_cnt = 0; }
    }

    const float* A   = z ? y : x;
    const int   woff = z ? DD : 0;
    float*      rdot = z ? g_ry  : g_rx;

    const int m0 = blockIdx.x * 64;
    const int h0 = blockIdx.y * 32;

    __shared__ __align__(16) float As[16][64];  // [k][m]
    __shared__ __align__(16) u64   Hd[16][32];  // [k][h] dup'd (w,w)
    __shared__ float rsum[64];

    const int tid = threadIdx.x;       // 128
    const int tx  = tid & 15;          // m quad: 4 m each
    const int ty  = tid >> 4;          // h quad: 4 h each (0..7)

    const int s_row = tid >> 2;        // 0..31
    const int s_q   = (tid & 3) * 4;   // k quad
    const bool h_ok = (h0 + s_row) < HH;

    float4 a0, a1, hw;

    a0 = *reinterpret_cast<const float4*>(&A[(m0 + s_row) * DD + s_q]);
    a1 = *reinterpret_cast<const float4*>(&A[(m0 + s_row + 32) * DD + s_q]);
    hw = make_float4(0.f, 0.f, 0.f, 0.f);
    if (h_ok)
        hw = *reinterpret_cast<const float4*>(&W1[(h0 + s_row) * (2 * DD) + woff + s_q]);

    u64 acc[4][2] = {};   // [ih][m-pair]

    const int NT = DD / 16;   // 25
    for (int t = 0; t < NT; t++) {
        As[s_q + 0][s_row] = a0.x; As[s_q + 1][s_row] = a0.y;
        As[s_q + 2][s_row] = a0.z; As[s_q + 3][s_row] = a0.w;
        As[s_q + 0][s_row + 32] = a1.x; As[s_q + 1][s_row + 32] = a1.y;
        As[s_q + 2][s_row + 32] = a1.z; As[s_q + 3][s_row + 32] = a1.w;
        u64 d0, d1, d2, d3;
        PACK2(d0, hw.x, hw.x); PACK2(d1, hw.y, hw.y);
        PACK2(d2, hw.z, hw.z); PACK2(d3, hw.w, hw.w);
        Hd[s_q + 0][s_row] = d0; Hd[s_q + 1][s_row] = d1;
        Hd[s_q + 2][s_row] = d2; Hd[s_q + 3][s_row] = d3;
        __syncthreads();

        if (t + 1 < NT) {
            int k0 = (t + 1) * 16;
            a0 = *reinterpret_cast<const float4*>(&A[(m0 + s_row) * DD + k0 + s_q]);
            a1 = *reinterpret_cast<const float4*>(&A[(m0 + s_row + 32) * DD + k0 + s_q]);
            if (h_ok)
                hw = *reinterpret_cast<const float4*>(&W1[(h0 + s_row) * (2 * DD) + woff + k0 + s_q]);
        }

        #pragma unroll
        for (int kk = 0; kk < 16; kk++) {
            ulonglong2 h01 = *reinterpret_cast<const ulonglong2*>(&Hd[kk][ty * 4 + 0]);
            ulonglong2 h23 = *reinterpret_cast<const ulonglong2*>(&Hd[kk][ty * 4 + 2]);
            ulonglong2 mm  = *reinterpret_cast<const ulonglong2*>(&As[kk][tx * 4]);
            FMA2(acc[0][0], h01.x, mm.x); FMA2(acc[0][1], h01.x, mm.y);
            FMA2(acc[1][0], h01.y, mm.x); FMA2(acc[1][1], h01.y, mm.y);
            FMA2(acc[2][0], h23.x, mm.x); FMA2(acc[2][1], h23.x, mm.y);
            FMA2(acc[3][0], h23.y, mm.x); FMA2(acc[3][1], h23.y, mm.y);
        }
        __syncthreads();
    }

    if (tid < 64) rsum[tid] = 0.f;
    __syncthreads();

    float part[4] = {0.f, 0.f, 0.f, 0.f};
    #pragma unroll
    for (int ih = 0; ih < 4; ih++) {
        const int h = h0 + ty * 4 + ih;
        const bool valid = h < HH;
        const float b  = (z && valid) ? b1[h] : 0.f;
        const float wv = valid ? W2[h] : 0.f;
        float2 p0 = *reinterpret_cast<float2*>(&acc[ih][0]);
        float2 p1 = *reinterpret_cast<float2*>(&acc[ih][1]);
        float v0 = p0.x + b, v1 = p0.y + b, v2 = p1.x + b, v3 = p1.y + b;
        if (valid) {
            if (z) {
                u64 q0, q1, q2, q3;
                PACK2(q0, v0, v0); PACK2(q1, v1, v1);
                PACK2(q2, v2, v2); PACK2(q3, v3, v3);
                ulonglong2* o = reinterpret_cast<ulonglong2*>(&g_hyTd[h * NS + m0 + tx * 4]);
                o[0] = make_ulonglong2(q0, q1);
                o[1] = make_ulonglong2(q2, q3);
            } else {
                *reinterpret_cast<float4*>(&g_hxT[h * NS + m0 + tx * 4]) =
                    make_float4(v0, v1, v2, v3);
            }
        }
        part[0] += v0 * wv; part[1] += v1 * wv;
        part[2] += v2 * wv; part[3] += v3 * wv;
    }
    #pragma unroll
    for (int mm = 0; mm < 4; mm++)
        atomicAdd(&rsum[tx * 4 + mm], part[mm]);
    __syncthreads();
    if (tid < 64) atomicAdd(&rdot[m0 + tid], rsum[tid]);
}

// ======================================================================
// Kernel 2: pair abs-dot, R12 structure + 4-way K-SPLIT.
// Grid (8, 16, 4) = 512 blocks, 128 threads. Each (i,j) tile has 4
// blocks covering tile ranges {7,7,6,6} of 16 k each (416 total).
// Partials stored to disjoint slices g_pA[split] (non-atomic,
// deterministic). Last-arriving block per tile sums the 4 slices via
// __ldcg and runs the fused epilogue. Thread tile 2i x 8j (16 outputs).
// ======================================================================
__global__ void __launch_bounds__(128)
pair_kernel(const float* __restrict__ b2p,
            float* __restrict__ out) {
    const int j0   = blockIdx.x * 64;
    const int i0   = blockIdx.y * 32;
    const int sp   = blockIdx.z;               // split 0..3
    const int tile = blockIdx.y * 8 + blockIdx.x;
    const int tid  = threadIdx.x;    // 128
    const int tx   = tid & 7;        // j octet: 8 j each
    const int ty   = tid >> 3;       // i pair: 2 i each (0..15)

    __shared__ __align__(16) u64 Xu[16][2][16];  // [kk][c][u64]
    __shared__ __align__(16) u64 Yd[16][32];     // [kk][i] dup'd (y,y)
    __shared__ __align__(16) u64 Wd[16];         // dup'd (w/2,w/2)

    const int s_k = tid >> 3;
    const int s_g = tid & 7;

    const u64* __restrict__ xp = reinterpret_cast<const u64*>(g_hxT);
    const int xbase = (j0 >> 1) + s_g * 4;
    const int ybase = i0 + s_g * 4;

    // split tile ranges: starts {0,7,14,20}, counts {7,7,6,6}
    const int tcnt   = (sp < 2) ? 7 : 6;
    const int tstart = (sp < 2) ? sp * 7 : 14 + (sp - 2) * 6;
    const int kb     = tstart * 16;

    ulonglong2 xr0, xr1, yr0, yr1;
    u64 wr = 0;

    xr0 = *reinterpret_cast<const ulonglong2*>(&xp[(kb + s_k) * 256 + xbase]);
    xr1 = *reinterpret_cast<const ulonglong2*>(&xp[(kb + s_k) * 256 + xbase + 2]);
    yr0 = *reinterpret_cast<const ulonglong2*>(&g_hyTd[(kb + s_k) * NS + ybase]);
    yr1 = *reinterpret_cast<const ulonglong2*>(&g_hyTd[(kb + s_k) * NS + ybase + 2]);
    if (tid < 16) wr = g_w2h[kb + tid];

    u64 acc[2][4] = {};   // [ii][j-quad-pair]: 8 independent chains

    for (int t = 0; t < tcnt; t++) {
        *reinterpret_cast<ulonglong2*>(&Xu[s_k][0][s_g * 2]) = xr0;
        *reinterpret_cast<ulonglong2*>(&Xu[s_k][1][s_g * 2]) = xr1;
        *reinterpret_cast<ulonglong2*>(&Yd[s_k][s_g * 4 + 0]) = yr0;
        *reinterpret_cast<ulonglong2*>(&Yd[s_k][s_g * 4 + 2]) = yr1;
        if (tid < 16) Wd[tid] = wr;
        __syncthreads();

        if (t + 1 < tcnt) {
            int k0 = kb + (t + 1) * 16;
            xr0 = *reinterpret_cast<const ulonglong2*>(&xp[(k0 + s_k) * 256 + xbase]);
            xr1 = *reinterpret_cast<const ulonglong2*>(&xp[(k0 + s_k) * 256 + xbase + 2]);
            yr0 = *reinterpret_cast<const ulonglong2*>(&g_hyTd[(k0 + s_k) * NS + ybase]);
            yr1 = *reinterpret_cast<const ulonglong2*>(&g_hyTd[(k0 + s_k) * NS + ybase + 2]);
            if (tid < 16) wr = g_w2h[k0 + tid];
        }

        #pragma unroll
        for (int kk = 0; kk < 16; kk++) {
            ulonglong2 x0 = *reinterpret_cast<const ulonglong2*>(&Xu[kk][0][tx * 2]);
            ulonglong2 x1 = *reinterpret_cast<const ulonglong2*>(&Xu[kk][1][tx * 2]);
            ulonglong2 yd = *reinterpret_cast<const ulonglong2*>(&Yd[kk][ty * 2]);
            u64 wv = Wd[kk];
            ABS_FMA2(acc[0][0], yd.x, x0.x, wv);
            ABS_FMA2(acc[0][1], yd.x, x0.y, wv);
            ABS_FMA2(acc[0][2], yd.x, x1.x, wv);
            ABS_FMA2(acc[0][3], yd.x, x1.y, wv);
            ABS_FMA2(acc[1][0], yd.y, x0.x, wv);
            ABS_FMA2(acc[1][1], yd.y, x0.y, wv);
            ABS_FMA2(acc[1][2], yd.y, x1.x, wv);
            ABS_FMA2(acc[1][3], yd.y, x1.y, wv);
        }
        __syncthreads();
    }

    // ---- store partial A to this split's slice (non-atomic) ----
    float* pa = g_pA[sp];
    #pragma unroll
    for (int ii = 0; ii < 2; ii++) {
        const int i = i0 + ty * 2 + ii;
        float2 c0 = *reinterpret_cast<float2*>(&acc[ii][0]);
        float2 c1 = *reinterpret_cast<float2*>(&acc[ii][1]);
        float2 c2 = *reinterpret_cast<float2*>(&acc[ii][2]);
        float2 c3 = *reinterpret_cast<float2*>(&acc[ii][3]);
        float* o = &pa[i * NS + j0 + tx * 8];
        *reinterpret_cast<float4*>(o + 0) = make_float4(c0.x, c0.y, c1.x, c1.y);
        *reinterpret_cast<float4*>(o + 4) = make_float4(c2.x, c2.y, c3.x, c3.y);
    }

    // ---- per-tile ticket: last of the 4 splits runs the epilogue ----
    __threadfence();
    __shared__ int tk;
    if (tid == 0) tk = atomicAdd(&g_tcnt[tile], 1);
    __syncthreads();
    if (tk != 3) return;
    if (tid == 0) g_tcnt[tile] = 0;   // reset for next graph replay

    // ---- fused epilogue (winner block; sums 4 slices via L2) ----
    const float b2 = b2p[0];
    const float4 rxa = *reinterpret_cast<const float4*>(&g_rx[j0 + tx * 8]);
    const float4 rxb = *reinterpret_cast<const float4*>(&g_rx[j0 + tx * 8 + 4]);
    const float rxq[8] = {rxa.x, rxa.y, rxa.z, rxa.w, rxb.x, rxb.y, rxb.z, rxb.w};
    float tSum = 0.f, dSum = 0.f;

    #pragma unroll
    for (int ii = 0; ii < 2; ii++) {
        const int i = i0 + ty * 2 + ii;
        const float ry = g_ry[i];
        float4 sa = make_float4(0.f, 0.f, 0.f, 0.f);
        float4 sb = make_float4(0.f, 0.f, 0.f, 0.f);
        #pragma unroll
        for (int s = 0; s < 4; s++) {
            const float4* p =
                reinterpret_cast<const float4*>(&g_pA[s][i * NS + j0 + tx * 8]);
            float4 u0 = __ldcg(p);
            float4 u1 = __ldcg(p + 1);
            sa.x += u0.x; sa.y += u0.y; sa.z += u0.z; sa.w += u0.w;
            sb.x += u1.x; sb.y += u1.y; sb.z += u1.z; sb.w += u1.w;
        }
        const float aq[8] = {sa.x, sa.y, sa.z, sa.w, sb.x, sb.y, sb.z, sb.w};
        float eRow = 0.f;
        #pragma unroll
        for (int q = 0; q < 8; q++) {
            float v = 0.5f * (ry + rxq[q]) + aq[q] + b2;
            float tt = fmaxf(v, 0.f) + log1pf(expf(-fabsf(v)));
            eRow += 1.f + expf(v);            // exp(softplus(v)) == 1 + e^v
            tSum += tt;
            if (j0 + tx * 8 + q == i) dSum += tt;
        }
        #pragma unroll
        for (int o = 4; o; o >>= 1)
            eRow += __shfl_down_sync(0xffffffffu, eRow, o, 8);
        if (tx == 0) atomicAdd(&g_expsum[i], eRow);
    }

    // block totals
    const int wid = tid >> 5, lane = tid & 31;
    #pragma unroll
    for (int o = 16; o; o >>= 1) {
        tSum += __shfl_down_sync(0xffffffffu, tSum, o);
        dSum += __shfl_down_sync(0xffffffffu, dSum, o);
    }
    __shared__ float wsum[4], wdia[4];
    if (lane == 0) { wsum[wid] = tSum; wdia[wid] = dSum; }
    __syncthreads();
    if (tid == 0) {
        float ts = wsum[0] + wsum[1] + wsum[2] + wsum[3];
        float ds = wdia[0] + wdia[1] + wdia[2] + wdia[3];
        atomicAdd(&g_tsum, (double)ts);
        atomicAdd(&g_dsum, (double)ds);
    }

    // ---- last tile-winner finalizes (double precision combine) ----
    __threadfence();
    __shared__ int ticket;
    if (tid == 0) ticket = atomicAdd(&g_cnt, 1);
    __syncthreads();
    if (ticket == 128 - 1) {
        #pragma unroll
        for (int r = 0; r < 4; r++) {
            g_rx[tid + r * 128] = 0.f;
            g_ry[tid + r * 128] = 0.f;
        }
        double ls = 0.0;
        #pragma unroll
        for (int r = 0; r < 4; r++)
            ls += log((double)g_expsum[tid + r * 128]);
        #pragma unroll
        for (int o = 16; o; o >>= 1)
            ls += __shfl_down_sync(0xffffffffu, ls, o);
        __shared__ double lw[4];
        if (lane == 0) lw[wid] = ls;
        __syncthreads();
        if (tid == 0) {
            double lsum = lw[0] + lw[1] + lw[2] + lw[3];
            const double n = (double)NS;
            double t0_mean = g_dsum / n;
            out[0] = (float)(t0_mean - (lsum / n - log(n)));   // lower bound
            out[1] = (float)(t0_mean - g_tsum / (n * n));      // upper bound
            g_cnt = 0;
        }
    }
}

// ======================================================================
extern "C" void kernel_launch(void* const* d_in, const int* in_sizes, int n_in,
                              void* d_out, int out_size) {
    const float* x  = (const float*)d_in[0];
    const float* y  = (const float*)d_in[1];
    const float* W1 = (const float*)d_in[2];
    const float* b1 = (const float*)d_in[3];
    const float* W2 = (const float*)d_in[4];
    const float* b2 = (const float*)d_in[5];
    float* out = (float*)d_out;

    dim3 ggrid(NS / 64, HP / 32, 2);          // (8, 13, 2) = 208 blocks
    gemm_h_kernel<<<ggrid, 128>>>(x, y, W1, b1, W2);

    dim3 pgrid(NS / 64, NS / 32, 4);          // (8, 16, 4) = 512 blocks
    pair_kernel<<<pgrid, 128>>>(b2, out);
}